// round 1
// baseline (speedup 1.0000x reference)
#include <cuda_runtime.h>
#include <math.h>

#define BQ 8
#define SEQ 1024
#define DIMV 512
#define HEADS 8
#define DHEAD 64
#define NHEADS 64        // BQ*HEADS
#define QKVW 1536        // 3*HEADS*DHEAD

#define LOG_MU (-6.93147180559945f)   // -log(1024)
#define LOG_NU (-6.93147180559945f)

// ---------------- scratch (device globals; no allocations allowed) ----------
__device__ float g_qkv[(size_t)BQ * SEQ * QKVW];          // 12.6M floats
__device__ float g_S[(size_t)NHEADS * SEQ * SEQ];         // 67.1M floats (dots)
__device__ float g_u[NHEADS * SEQ];
__device__ float g_v[NHEADS * SEQ];
__device__ float g_ho[(size_t)BQ * SEQ * DIMV];           // head-merged attn@V

// ---------------- generic 128x128x8 fp32 GEMM, 8x8 per thread ---------------
// C[M,Nn] = A[M,K] @ B[K,Nn] (+ bias). Requires M%128==0, Nn%128==0, K%8==0.
__global__ __launch_bounds__(256) void sgemm128(
    const float* __restrict__ A, const float* __restrict__ Bm,
    float* __restrict__ C, int M, int Nn, int K, const float* __restrict__ bias)
{
    __shared__ float As[8][128];
    __shared__ float Bs[8][128];
    const int t = threadIdx.x;
    const int m0 = blockIdx.y * 128, n0 = blockIdx.x * 128;
    const int alr = t >> 1, alc = (t & 1) * 4;     // A tile: 128 rows x 8 cols
    const int blr = t >> 5, blc = (t & 31) * 4;    // B tile: 8 rows x 128 cols
    const int tx = t & 15, ty = t >> 4;

    float acc[8][8];
#pragma unroll
    for (int r = 0; r < 8; r++)
#pragma unroll
        for (int c = 0; c < 8; c++) acc[r][c] = 0.f;

    for (int k0 = 0; k0 < K; k0 += 8) {
        float4 av = *(const float4*)(A + (size_t)(m0 + alr) * K + k0 + alc);
        As[alc + 0][alr] = av.x; As[alc + 1][alr] = av.y;
        As[alc + 2][alr] = av.z; As[alc + 3][alr] = av.w;
        *(float4*)(&Bs[blr][blc]) =
            *(const float4*)(Bm + (size_t)(k0 + blr) * Nn + n0 + blc);
        __syncthreads();
#pragma unroll
        for (int kk = 0; kk < 8; kk++) {
            float a[8], b[8];
#pragma unroll
            for (int r = 0; r < 4; r++) {
                a[r]     = As[kk][ty * 4 + r];
                a[4 + r] = As[kk][64 + ty * 4 + r];
            }
#pragma unroll
            for (int c = 0; c < 4; c++) {
                b[c]     = Bs[kk][tx * 4 + c];
                b[4 + c] = Bs[kk][64 + tx * 4 + c];
            }
#pragma unroll
            for (int r = 0; r < 8; r++)
#pragma unroll
                for (int c = 0; c < 8; c++) acc[r][c] = fmaf(a[r], b[c], acc[r][c]);
        }
        __syncthreads();
    }
#pragma unroll
    for (int r = 0; r < 8; r++) {
        int gr = m0 + ((r < 4) ? (ty * 4 + r) : (64 + ty * 4 + (r - 4)));
#pragma unroll
        for (int half = 0; half < 2; half++) {
            int gc = n0 + ((half == 0) ? tx * 4 : 64 + tx * 4);
            float4 o;
            o.x = acc[r][half * 4 + 0]; o.y = acc[r][half * 4 + 1];
            o.z = acc[r][half * 4 + 2]; o.w = acc[r][half * 4 + 3];
            if (bias) {
                o.x += bias[gc]; o.y += bias[gc + 1];
                o.z += bias[gc + 2]; o.w += bias[gc + 3];
            }
            *(float4*)(C + (size_t)gr * Nn + gc) = o;
        }
    }
}

// ---------------- per-head dots: S[i,j] = SCALE * sum_c q[i,c]*k[j,c] --------
__global__ __launch_bounds__(256) void qk_dots(
    const float* __restrict__ qkv, float* __restrict__ S)
{
    const int bh = blockIdx.z, b = bh >> 3, h = bh & 7;
    const int i0 = blockIdx.y * 128, j0 = blockIdx.x * 128;
    const float* qbase = qkv + (size_t)b * SEQ * QKVW + h * DHEAD;         // q
    const float* kbase = qkv + (size_t)b * SEQ * QKVW + 512 + h * DHEAD;   // k

    __shared__ float Qs[8][128];
    __shared__ float Ks[8][128];
    const int t = threadIdx.x;
    const int lr = t >> 1, lc = (t & 1) * 4;
    const int tx = t & 15, ty = t >> 4;

    float acc[8][8];
#pragma unroll
    for (int r = 0; r < 8; r++)
#pragma unroll
        for (int c = 0; c < 8; c++) acc[r][c] = 0.f;

    for (int k0 = 0; k0 < DHEAD; k0 += 8) {
        float4 qv = *(const float4*)(qbase + (size_t)(i0 + lr) * QKVW + k0 + lc);
        Qs[lc + 0][lr] = qv.x; Qs[lc + 1][lr] = qv.y;
        Qs[lc + 2][lr] = qv.z; Qs[lc + 3][lr] = qv.w;
        float4 kv = *(const float4*)(kbase + (size_t)(j0 + lr) * QKVW + k0 + lc);
        Ks[lc + 0][lr] = kv.x; Ks[lc + 1][lr] = kv.y;
        Ks[lc + 2][lr] = kv.z; Ks[lc + 3][lr] = kv.w;
        __syncthreads();
#pragma unroll
        for (int kk = 0; kk < 8; kk++) {
            float a[8], b[8];
#pragma unroll
            for (int r = 0; r < 4; r++) {
                a[r]     = Qs[kk][ty * 4 + r];
                a[4 + r] = Qs[kk][64 + ty * 4 + r];
            }
#pragma unroll
            for (int c = 0; c < 4; c++) {
                b[c]     = Ks[kk][tx * 4 + c];
                b[4 + c] = Ks[kk][64 + tx * 4 + c];
            }
#pragma unroll
            for (int r = 0; r < 8; r++)
#pragma unroll
                for (int c = 0; c < 8; c++) acc[r][c] = fmaf(a[r], b[c], acc[r][c]);
        }
        __syncthreads();
    }
    float* Sp = S + (size_t)bh * SEQ * SEQ;
#pragma unroll
    for (int r = 0; r < 8; r++) {
        int gi = i0 + ((r < 4) ? (ty * 4 + r) : (64 + ty * 4 + (r - 4)));
#pragma unroll
        for (int half = 0; half < 2; half++) {
            int gj = j0 + ((half == 0) ? tx * 4 : 64 + tx * 4);
            float4 o;
            o.x = acc[r][half * 4 + 0] * 0.125f;
            o.y = acc[r][half * 4 + 1] * 0.125f;
            o.z = acc[r][half * 4 + 2] * 0.125f;
            o.w = acc[r][half * 4 + 3] * 0.125f;
            *(float4*)(Sp + (size_t)gi * SEQ + gj) = o;
        }
    }
}

// ---------------- Sinkhorn passes (eps = 1) ----------------------------------
// u_i = log_mu - LSE_j( v_j - S_ij )
__global__ __launch_bounds__(256) void row_lse(
    const float* __restrict__ S, const float* __restrict__ v, float* __restrict__ u)
{
    const int bh = blockIdx.y, i = blockIdx.x;
    const float* Sr = S + (size_t)bh * SEQ * SEQ + (size_t)i * SEQ;
    const float* vp = v + bh * SEQ;
    const int t = threadIdx.x;

    float m = -1e30f, s = 0.f;
    for (int j = t; j < SEQ; j += 256) {
        float x = vp[j] - Sr[j];
        if (x > m) { s = s * __expf(m - x) + 1.f; m = x; }
        else       { s += __expf(x - m); }
    }
#pragma unroll
    for (int o = 16; o > 0; o >>= 1) {
        float m2 = __shfl_xor_sync(0xffffffffu, m, o);
        float s2 = __shfl_xor_sync(0xffffffffu, s, o);
        float M = fmaxf(m, m2);
        s = s * __expf(m - M) + s2 * __expf(m2 - M);
        m = M;
    }
    __shared__ float sm[8], ss[8];
    if ((t & 31) == 0) { sm[t >> 5] = m; ss[t >> 5] = s; }
    __syncthreads();
    if (t == 0) {
        float M = sm[0], Sa = ss[0];
        for (int w = 1; w < 8; w++) {
            float mm = fmaxf(M, sm[w]);
            Sa = Sa * __expf(M - mm) + ss[w] * __expf(sm[w] - mm);
            M = mm;
        }
        u[bh * SEQ + i] = LOG_MU - (M + logf(Sa));
    }
}

// v_j = log_nu - LSE_i( u_i - S_ij )
__global__ __launch_bounds__(256) void col_lse(
    const float* __restrict__ S, const float* __restrict__ u, float* __restrict__ v)
{
    const int bh = blockIdx.y;
    const int lane = threadIdx.x & 31;
    const int ty = threadIdx.x >> 5;          // 0..7
    const int j = blockIdx.x * 32 + lane;
    const float* Sp = S + (size_t)bh * SEQ * SEQ;
    const float* up = u + bh * SEQ;

    float m = -1e30f, s = 0.f;
    for (int i = ty; i < SEQ; i += 8) {
        float x = up[i] - Sp[(size_t)i * SEQ + j];
        if (x > m) { s = s * __expf(m - x) + 1.f; m = x; }
        else       { s += __expf(x - m); }
    }
    __shared__ float sm[8][32], ss[8][32];
    sm[ty][lane] = m; ss[ty][lane] = s;
    __syncthreads();
    if (ty == 0) {
        float M = sm[0][lane], Sa = ss[0][lane];
        for (int w = 1; w < 8; w++) {
            float mm = fmaxf(M, sm[w][lane]);
            Sa = Sa * __expf(M - mm) + ss[w][lane] * __expf(sm[w][lane] - mm);
            M = mm;
        }
        v[bh * SEQ + j] = LOG_NU - (M + logf(Sa));
    }
}

__global__ void init_zero(float* __restrict__ p)
{
    p[blockIdx.x * 256 + threadIdx.x] = 0.f;
}

// ---------------- fused: attn = exp(u+v-S)*n (write), ho = attn @ V ----------
__global__ __launch_bounds__(256) void attn_av(
    const float* __restrict__ S, const float* __restrict__ u,
    const float* __restrict__ v, const float* __restrict__ qkv,
    float* __restrict__ attn, float* __restrict__ ho, int write_attn)
{
    const int bh = blockIdx.y, b = bh >> 3, h = bh & 7;
    const int i0 = blockIdx.x * 64;
    __shared__ float At[64][65];
    __shared__ float Vs[64][65];
    const int t = threadIdx.x;
    const int tx = t & 15, ty = t >> 4;
    const int lc = t & 63, lrb = t >> 6;      // loader: col 0..63, row base 0..3

    const float* vbase = qkv + (size_t)b * SEQ * QKVW + 1024 + h * DHEAD;
    const float* up = u + bh * SEQ;
    const float* vp = v + bh * SEQ;
    const float* Sp = S + (size_t)bh * SEQ * SEQ;
    float* ap = attn + (size_t)bh * SEQ * SEQ;

    float acc[4][4];
#pragma unroll
    for (int r = 0; r < 4; r++)
#pragma unroll
        for (int c = 0; c < 4; c++) acc[r][c] = 0.f;

    for (int jt = 0; jt < 16; jt++) {
        const int j0 = jt * 64;
        const float vj = vp[j0 + lc];
#pragma unroll
        for (int rr = 0; rr < 16; rr++) {
            const int r = lrb + 4 * rr;       // 0..63
            Vs[r][lc] = vbase[(size_t)(j0 + r) * QKVW + lc];
            float val = __expf(up[i0 + r] + vj - Sp[(size_t)(i0 + r) * SEQ + j0 + lc])
                        * 1024.0f;
            At[r][lc] = val;
            if (write_attn) ap[(size_t)(i0 + r) * SEQ + j0 + lc] = val;
        }
        __syncthreads();
#pragma unroll
        for (int kk = 0; kk < 64; kk++) {
            float bb[4];
#pragma unroll
            for (int c = 0; c < 4; c++) bb[c] = Vs[kk][tx * 4 + c];
#pragma unroll
            for (int r = 0; r < 4; r++) {
                float a = At[ty * 4 + r][kk];
#pragma unroll
                for (int c = 0; c < 4; c++) acc[r][c] = fmaf(a, bb[c], acc[r][c]);
            }
        }
        __syncthreads();
    }
#pragma unroll
    for (int r = 0; r < 4; r++)
#pragma unroll
        for (int c = 0; c < 4; c++)
            ho[(size_t)(b * SEQ + i0 + ty * 4 + r) * DIMV + h * DHEAD + tx * 4 + c] =
                acc[r][c];
}

// ---------------- launcher ---------------------------------------------------
extern "C" void kernel_launch(void* const* d_in, const int* in_sizes, int n_in,
                              void* d_out, int out_size)
{
    const float* x    = (const float*)d_in[0];   // [8,1024,512]
    const float* Wqkv = (const float*)d_in[1];   // [512,1536]
    const float* Wout = (const float*)d_in[2];   // [512,512]
    const float* bout = (const float*)d_in[3];   // [512]
    float* out = (float*)d_out;

    float *qkvp, *Sp, *up, *vp, *hop;
    cudaGetSymbolAddress((void**)&qkvp, g_qkv);
    cudaGetSymbolAddress((void**)&Sp,   g_S);
    cudaGetSymbolAddress((void**)&up,   g_u);
    cudaGetSymbolAddress((void**)&vp,   g_v);
    cudaGetSymbolAddress((void**)&hop,  g_ho);

    const size_t FIN = (size_t)BQ * SEQ * DIMV;        // 4,194,304
    const size_t ATT = (size_t)NHEADS * SEQ * SEQ;     // 67,108,864
    float* fin_ptr = 0;
    float* attn_ptr = 0;
    if ((size_t)out_size >= FIN + ATT) { fin_ptr = out; attn_ptr = out + FIN; }
    else if ((size_t)out_size == ATT)  { attn_ptr = out; }
    else                               { fin_ptr = out; }

    // 1) qkv = x @ W_qkv
    sgemm128<<<dim3(QKVW / 128, (BQ * SEQ) / 128), 256>>>(
        x, Wqkv, qkvp, BQ * SEQ, QKVW, DIMV, (const float*)0);

    // 2) S = scale * q k^T per head
    qk_dots<<<dim3(SEQ / 128, SEQ / 128, NHEADS), 256>>>(qkvp, Sp);

    // 3) Sinkhorn (eps=1, 3 iterations)
    init_zero<<<(NHEADS * SEQ) / 256, 256>>>(vp);
    for (int it = 0; it < 3; it++) {
        row_lse<<<dim3(SEQ, NHEADS), 256>>>(Sp, vp, up);
        col_lse<<<dim3(SEQ / 32, NHEADS), 256>>>(Sp, up, vp);
    }

    // 4) attn = exp(u+v-S)*n (written to output) and ho = attn @ V
    attn_av<<<dim3(SEQ / 64, NHEADS), 256>>>(
        Sp, up, vp, qkvp, attn_ptr ? attn_ptr : Sp, hop, attn_ptr ? 1 : 0);

    // 5) final = ho @ W_out + b_out
    if (fin_ptr)
        sgemm128<<<dim3(DIMV / 128, (BQ * SEQ) / 128), 256>>>(
            hop, Wout, fin_ptr, BQ * SEQ, DIMV, DIMV, bout);
}

// round 2
// speedup vs baseline: 1.4302x; 1.4302x over previous
#include <cuda_runtime.h>
#include <math.h>

#define BQ 8
#define SEQ 1024
#define DIMV 512
#define HEADS 8
#define DHEAD 64
#define NHEADS 64        // BQ*HEADS
#define QKVW 1536        // 3*HEADS*DHEAD

#define MU_C (1.0f/1024.0f)
#define NU_C (1.0f/1024.0f)

// ---------------- scratch (device globals; no allocations allowed) ----------
__device__ float g_qkv[(size_t)BQ * SEQ * QKVW];          // 12.6M floats
__device__ float g_E[(size_t)NHEADS * SEQ * SEQ];         // 67.1M floats  E=exp(-C)
__device__ float g_r[NHEADS * SEQ];
__device__ float g_c[NHEADS * SEQ];
__device__ float g_rowsum[NHEADS * SEQ];
__device__ float g_colsum[NHEADS * SEQ];
__device__ float g_ho[(size_t)BQ * SEQ * DIMV];           // head-merged attn@V

// ---------------- generic 128x128x8 fp32 GEMM, 8x8 per thread ---------------
__global__ __launch_bounds__(256) void sgemm128(
    const float* __restrict__ A, const float* __restrict__ Bm,
    float* __restrict__ C, int M, int Nn, int K, const float* __restrict__ bias)
{
    __shared__ float As[8][128];
    __shared__ float Bs[8][128];
    const int t = threadIdx.x;
    const int m0 = blockIdx.y * 128, n0 = blockIdx.x * 128;
    const int alr = t >> 1, alc = (t & 1) * 4;
    const int blr = t >> 5, blc = (t & 31) * 4;
    const int tx = t & 15, ty = t >> 4;

    float acc[8][8];
#pragma unroll
    for (int r = 0; r < 8; r++)
#pragma unroll
        for (int c = 0; c < 8; c++) acc[r][c] = 0.f;

    for (int k0 = 0; k0 < K; k0 += 8) {
        float4 av = *(const float4*)(A + (size_t)(m0 + alr) * K + k0 + alc);
        As[alc + 0][alr] = av.x; As[alc + 1][alr] = av.y;
        As[alc + 2][alr] = av.z; As[alc + 3][alr] = av.w;
        *(float4*)(&Bs[blr][blc]) =
            *(const float4*)(Bm + (size_t)(k0 + blr) * Nn + n0 + blc);
        __syncthreads();
#pragma unroll
        for (int kk = 0; kk < 8; kk++) {
            float a[8], b[8];
#pragma unroll
            for (int r = 0; r < 4; r++) {
                a[r]     = As[kk][ty * 4 + r];
                a[4 + r] = As[kk][64 + ty * 4 + r];
            }
#pragma unroll
            for (int c = 0; c < 4; c++) {
                b[c]     = Bs[kk][tx * 4 + c];
                b[4 + c] = Bs[kk][64 + tx * 4 + c];
            }
#pragma unroll
            for (int r = 0; r < 8; r++)
#pragma unroll
                for (int c = 0; c < 8; c++) acc[r][c] = fmaf(a[r], b[c], acc[r][c]);
        }
        __syncthreads();
    }
#pragma unroll
    for (int r = 0; r < 8; r++) {
        int gr = m0 + ((r < 4) ? (ty * 4 + r) : (64 + ty * 4 + (r - 4)));
#pragma unroll
        for (int half = 0; half < 2; half++) {
            int gc = n0 + ((half == 0) ? tx * 4 : 64 + tx * 4);
            float4 o;
            o.x = acc[r][half * 4 + 0]; o.y = acc[r][half * 4 + 1];
            o.z = acc[r][half * 4 + 2]; o.w = acc[r][half * 4 + 3];
            if (bias) {
                o.x += bias[gc]; o.y += bias[gc + 1];
                o.z += bias[gc + 2]; o.w += bias[gc + 3];
            }
            *(float4*)(C + (size_t)gr * Nn + gc) = o;
        }
    }
}

// -------- per-head dots -> E = exp(-scale*dots), fused first row-sum --------
__global__ __launch_bounds__(256) void qk_dots_exp(
    const float* __restrict__ qkv, float* __restrict__ E,
    float* __restrict__ rowsum)
{
    const int bh = blockIdx.z, b = bh >> 3, h = bh & 7;
    const int i0 = blockIdx.y * 128, j0 = blockIdx.x * 128;
    const float* qbase = qkv + (size_t)b * SEQ * QKVW + h * DHEAD;
    const float* kbase = qkv + (size_t)b * SEQ * QKVW + 512 + h * DHEAD;

    __shared__ float Qs[8][128];
    __shared__ float Ks[8][128];
    const int t = threadIdx.x;
    const int lr = t >> 1, lc = (t & 1) * 4;
    const int tx = t & 15, ty = t >> 4;

    float acc[8][8];
#pragma unroll
    for (int r = 0; r < 8; r++)
#pragma unroll
        for (int c = 0; c < 8; c++) acc[r][c] = 0.f;

    for (int k0 = 0; k0 < DHEAD; k0 += 8) {
        float4 qv = *(const float4*)(qbase + (size_t)(i0 + lr) * QKVW + k0 + lc);
        Qs[lc + 0][lr] = qv.x; Qs[lc + 1][lr] = qv.y;
        Qs[lc + 2][lr] = qv.z; Qs[lc + 3][lr] = qv.w;
        float4 kv = *(const float4*)(kbase + (size_t)(j0 + lr) * QKVW + k0 + lc);
        Ks[lc + 0][lr] = kv.x; Ks[lc + 1][lr] = kv.y;
        Ks[lc + 2][lr] = kv.z; Ks[lc + 3][lr] = kv.w;
        __syncthreads();
#pragma unroll
        for (int kk = 0; kk < 8; kk++) {
            float a[8], b[8];
#pragma unroll
            for (int r = 0; r < 4; r++) {
                a[r]     = Qs[kk][ty * 4 + r];
                a[4 + r] = Qs[kk][64 + ty * 4 + r];
            }
#pragma unroll
            for (int c = 0; c < 4; c++) {
                b[c]     = Ks[kk][tx * 4 + c];
                b[4 + c] = Ks[kk][64 + tx * 4 + c];
            }
#pragma unroll
            for (int r = 0; r < 8; r++)
#pragma unroll
                for (int c = 0; c < 8; c++) acc[r][c] = fmaf(a[r], b[c], acc[r][c]);
        }
        __syncthreads();
    }
    float* Ep = E + (size_t)bh * SEQ * SEQ;
    float rsum[8];
#pragma unroll
    for (int r = 0; r < 8; r++) rsum[r] = 0.f;
#pragma unroll
    for (int r = 0; r < 8; r++) {
        int gi = i0 + ((r < 4) ? (ty * 4 + r) : (64 + ty * 4 + (r - 4)));
#pragma unroll
        for (int half = 0; half < 2; half++) {
            int gj = j0 + ((half == 0) ? tx * 4 : 64 + tx * 4);
            float4 o;
            o.x = __expf(-0.125f * acc[r][half * 4 + 0]);
            o.y = __expf(-0.125f * acc[r][half * 4 + 1]);
            o.z = __expf(-0.125f * acc[r][half * 4 + 2]);
            o.w = __expf(-0.125f * acc[r][half * 4 + 3]);
            rsum[r] += o.x + o.y + o.z + o.w;
            *(float4*)(Ep + (size_t)gi * SEQ + gj) = o;
        }
    }
    // reduce rsum across the 16 tx lanes sharing each ty (same half-warp)
#pragma unroll
    for (int r = 0; r < 8; r++) {
#pragma unroll
        for (int off = 1; off < 16; off <<= 1)
            rsum[r] += __shfl_xor_sync(0xffffffffu, rsum[r], off);
    }
    if (tx == 0) {
#pragma unroll
        for (int r = 0; r < 8; r++) {
            int gi = i0 + ((r < 4) ? (ty * 4 + r) : (64 + ty * 4 + (r - 4)));
            atomicAdd(&rowsum[bh * SEQ + gi], rsum[r]);
        }
    }
}

// ---------------- linear-domain Sinkhorn matvec passes ----------------------
// r_i = MU / sum_j E_ij * c_j      (one warp per row)
__global__ __launch_bounds__(256) void rowpass(
    const float* __restrict__ E, const float* __restrict__ c,
    float* __restrict__ r)
{
    const int bh = blockIdx.y;
    const int t = threadIdx.x, lane = t & 31, w = t >> 5;
    const int row = blockIdx.x * 8 + w;
    __shared__ float cs[SEQ];
    *(float4*)(&cs[t * 4]) = *(const float4*)(c + bh * SEQ + t * 4);
    __syncthreads();

    const float* Er = E + (size_t)bh * SEQ * SEQ + (size_t)row * SEQ;
    float acc = 0.f;
#pragma unroll
    for (int it = 0; it < 8; it++) {
        int j = it * 128 + lane * 4;
        float4 e = *(const float4*)(Er + j);
        acc += e.x * cs[j] + e.y * cs[j + 1] + e.z * cs[j + 2] + e.w * cs[j + 3];
    }
#pragma unroll
    for (int o = 16; o > 0; o >>= 1)
        acc += __shfl_xor_sync(0xffffffffu, acc, o);
    if (lane == 0) r[bh * SEQ + row] = MU_C / acc;
}

// colsum_j += sum_i E_ij * r_i  (partial over 128-row chunk, atomic combine)
__global__ __launch_bounds__(256) void colpass(
    const float* __restrict__ E, const float* __restrict__ r,
    float* __restrict__ colsum)
{
    const int bh = blockIdx.y;
    const int i0 = blockIdx.x * 128;
    const int t = threadIdx.x;
    __shared__ float rs[128];
    if (t < 128) rs[t] = r[bh * SEQ + i0 + t];
    __syncthreads();

    const float* Ep = E + (size_t)bh * SEQ * SEQ + (size_t)i0 * SEQ;
    const int j = t * 4;
    float ax = 0.f, ay = 0.f, az = 0.f, aw = 0.f;
#pragma unroll 4
    for (int i = 0; i < 128; i++) {
        float4 e = *(const float4*)(Ep + (size_t)i * SEQ + j);
        float rv = rs[i];
        ax = fmaf(e.x, rv, ax); ay = fmaf(e.y, rv, ay);
        az = fmaf(e.z, rv, az); aw = fmaf(e.w, rv, aw);
    }
    atomicAdd(&colsum[bh * SEQ + j + 0], ax);
    atomicAdd(&colsum[bh * SEQ + j + 1], ay);
    atomicAdd(&colsum[bh * SEQ + j + 2], az);
    atomicAdd(&colsum[bh * SEQ + j + 3], aw);
}

__global__ void init_sums(float* __restrict__ rowsum, float* __restrict__ colsum)
{
    int i = blockIdx.x * 256 + threadIdx.x;
    rowsum[i] = 0.f;
    colsum[i] = 0.f;
}

__global__ void recipR(const float* __restrict__ rowsum, float* __restrict__ r)
{
    int i = blockIdx.x * 256 + threadIdx.x;
    r[i] = MU_C / rowsum[i];
}

__global__ void recipC(float* __restrict__ colsum, float* __restrict__ c)
{
    int i = blockIdx.x * 256 + threadIdx.x;
    c[i] = NU_C / colsum[i];
    colsum[i] = 0.f;
}

// ------------- fused: attn = r_i*E_ij*c_j*n (write), ho = attn @ V ----------
__global__ __launch_bounds__(256) void attn_av(
    const float* __restrict__ E, const float* __restrict__ r,
    const float* __restrict__ c, const float* __restrict__ qkv,
    float* __restrict__ attn, float* __restrict__ ho, int write_attn)
{
    const int bh = blockIdx.y, b = bh >> 3, h = bh & 7;
    const int i0 = blockIdx.x * 64;
    __shared__ float At[64][65];
    __shared__ float Vs[64][65];
    __shared__ float rn[64];
    const int t = threadIdx.x;
    const int tx = t & 15, ty = t >> 4;
    const int lc = t & 63, lrb = t >> 6;

    const float* vbase = qkv + (size_t)b * SEQ * QKVW + 1024 + h * DHEAD;
    const float* rp = r + bh * SEQ;
    const float* cp = c + bh * SEQ;
    const float* Ep = E + (size_t)bh * SEQ * SEQ;
    float* ap = attn + (size_t)bh * SEQ * SEQ;

    if (t < 64) rn[t] = rp[i0 + t] * 1024.0f;
    __syncthreads();

    float acc[4][4];
#pragma unroll
    for (int rr = 0; rr < 4; rr++)
#pragma unroll
        for (int cc = 0; cc < 4; cc++) acc[rr][cc] = 0.f;

    for (int jt = 0; jt < 16; jt++) {
        const int j0 = jt * 64;
        const float cj = cp[j0 + lc];
#pragma unroll
        for (int rr = 0; rr < 16; rr++) {
            const int rw = lrb + 4 * rr;
            Vs[rw][lc] = vbase[(size_t)(j0 + rw) * QKVW + lc];
            float val = rn[rw] * Ep[(size_t)(i0 + rw) * SEQ + j0 + lc] * cj;
            At[rw][lc] = val;
            if (write_attn) ap[(size_t)(i0 + rw) * SEQ + j0 + lc] = val;
        }
        __syncthreads();
#pragma unroll
        for (int kk = 0; kk < 64; kk++) {
            float bb[4];
#pragma unroll
            for (int cc = 0; cc < 4; cc++) bb[cc] = Vs[kk][tx * 4 + cc];
#pragma unroll
            for (int rr = 0; rr < 4; rr++) {
                float a = At[ty * 4 + rr][kk];
#pragma unroll
                for (int cc = 0; cc < 4; cc++) acc[rr][cc] = fmaf(a, bb[cc], acc[rr][cc]);
            }
        }
        __syncthreads();
    }
#pragma unroll
    for (int rr = 0; rr < 4; rr++)
#pragma unroll
        for (int cc = 0; cc < 4; cc++)
            ho[(size_t)(b * SEQ + i0 + ty * 4 + rr) * DIMV + h * DHEAD + tx * 4 + cc] =
                acc[rr][cc];
}

// ---------------- launcher ---------------------------------------------------
extern "C" void kernel_launch(void* const* d_in, const int* in_sizes, int n_in,
                              void* d_out, int out_size)
{
    const float* x    = (const float*)d_in[0];   // [8,1024,512]
    const float* Wqkv = (const float*)d_in[1];   // [512,1536]
    const float* Wout = (const float*)d_in[2];   // [512,512]
    const float* bout = (const float*)d_in[3];   // [512]
    float* out = (float*)d_out;

    float *qkvp, *Ep, *rp, *cp, *rsp, *csp, *hop;
    cudaGetSymbolAddress((void**)&qkvp, g_qkv);
    cudaGetSymbolAddress((void**)&Ep,   g_E);
    cudaGetSymbolAddress((void**)&rp,   g_r);
    cudaGetSymbolAddress((void**)&cp,   g_c);
    cudaGetSymbolAddress((void**)&rsp,  g_rowsum);
    cudaGetSymbolAddress((void**)&csp,  g_colsum);
    cudaGetSymbolAddress((void**)&hop,  g_ho);

    const size_t FIN = (size_t)BQ * SEQ * DIMV;        // 4,194,304
    const size_t ATT = (size_t)NHEADS * SEQ * SEQ;     // 67,108,864
    float* fin_ptr = 0;
    float* attn_ptr = 0;
    if ((size_t)out_size >= FIN + ATT) { fin_ptr = out; attn_ptr = out + FIN; }
    else if ((size_t)out_size == ATT)  { attn_ptr = out; }
    else                               { fin_ptr = out; }

    const int NV = NHEADS * SEQ;   // 65536

    // 0) zero accumulators
    init_sums<<<NV / 256, 256>>>(rsp, csp);

    // 1) qkv = x @ W_qkv
    sgemm128<<<dim3(QKVW / 128, (BQ * SEQ) / 128), 256>>>(
        x, Wqkv, qkvp, BQ * SEQ, QKVW, DIMV, (const float*)0);

    // 2) E = exp(-scale*q k^T), fused row-sum for iteration-1 u-update (c0=1)
    qk_dots_exp<<<dim3(SEQ / 128, SEQ / 128, NHEADS), 256>>>(qkvp, Ep, rsp);
    recipR<<<NV / 256, 256>>>(rsp, rp);

    // 3) linear-domain Sinkhorn: col1, row2, col2, row3, col3
    colpass<<<dim3(SEQ / 128, NHEADS), 256>>>(Ep, rp, csp);
    recipC<<<NV / 256, 256>>>(csp, cp);

    rowpass<<<dim3(SEQ / 8, NHEADS), 256>>>(Ep, cp, rp);
    colpass<<<dim3(SEQ / 128, NHEADS), 256>>>(Ep, rp, csp);
    recipC<<<NV / 256, 256>>>(csp, cp);

    rowpass<<<dim3(SEQ / 8, NHEADS), 256>>>(Ep, cp, rp);
    colpass<<<dim3(SEQ / 128, NHEADS), 256>>>(Ep, rp, csp);
    recipC<<<NV / 256, 256>>>(csp, cp);

    // 4) attn = r*E*c*n (written to output) and ho = attn @ V
    attn_av<<<dim3(SEQ / 64, NHEADS), 256>>>(
        Ep, rp, cp, qkvp, attn_ptr ? attn_ptr : Ep, hop, attn_ptr ? 1 : 0);

    // 5) final = ho @ W_out + b_out
    if (fin_ptr)
        sgemm128<<<dim3(DIMV / 128, (BQ * SEQ) / 128), 256>>>(
            hop, Wout, fin_ptr, BQ * SEQ, DIMV, DIMV, bout);
}